// round 7
// baseline (speedup 1.0000x reference)
#include <cuda_runtime.h>
#include <math.h>

#define BATCH 2
#define CDIM  512
#define HEADS 8
#define DHEAD 64
#define NPIX  4096
#define KTOP  32
#define GDIM  128

typedef unsigned long long ull;

#define NEG_INF (__int_as_float(0xff800000))

// ---------------- scratch (device globals; no allocation allowed) ----------------
__device__ float g_q[BATCH*HEADS*DHEAD*NPIX];   // [b][h][d][n]
__device__ float g_k[BATCH*HEADS*DHEAD*NPIX];   // [b][h][d][n]
__device__ float g_v[BATCH*HEADS*NPIX*DHEAD];   // [b][h][n][d]
__device__ float g_g1[BATCH*NPIX*GDIM];         // [b][n][o]  gate hidden (bias applied)
__device__ float g_attn[BATCH*CDIM*NPIX];       // [b][c][n]  attention output (pre-proj)
__device__ int   g_kdyn[BATCH*NPIX];

// ---------------- f32x2 helpers (sm_103a packed fp32) ----------------
__device__ __forceinline__ ull fma2(ull a, ull b, ull c) {
    ull d;
    asm("fma.rn.f32x2 %0, %1, %2, %3;" : "=l"(d) : "l"(a), "l"(b), "l"(c));
    return d;
}
__device__ __forceinline__ ull dup2(float x) {
    ull r; unsigned u = __float_as_uint(x);
    asm("mov.b64 %0, {%1, %1};" : "=l"(r) : "r"(u));
    return r;
}
__device__ __forceinline__ float lo2(ull x) { return __uint_as_float((unsigned)x); }
__device__ __forceinline__ float hi2(ull x) { return __uint_as_float((unsigned)(x >> 32)); }

// =====================================================================
// Kernel 1: fused qkv conv (1536 rows) + gate conv1 (128 rows) GEMM.
// k-tile = 32 (halved barrier count), float4 loads for both tiles.
// Accumulation order over c unchanged -> outputs bit-identical to R2.
// =====================================================================
__global__ void __launch_bounds__(128) k_qkv(const float* __restrict__ x,
                                             const float* __restrict__ w_qkv,
                                             const float* __restrict__ w_g1,
                                             const float* __restrict__ b_g1)
{
    __shared__ __align__(16) float As[32 * 68];
    __shared__ __align__(16) float Bs[32 * 64];
    const int b  = blockIdx.z;
    const int o0 = blockIdx.y * 64;
    const int n0 = blockIdx.x * 64;
    const int t  = threadIdx.x;
    const int to = (t >> 3) * 4;
    const int tn = (t & 7) * 8;
    const float* xb = x + (size_t)b * CDIM * NPIX;

    ull acc[4][4];
#pragma unroll
    for (int i = 0; i < 4; i++)
#pragma unroll
        for (int p = 0; p < 4; p++) acc[i][p] = 0ULL;

    for (int c0 = 0; c0 < CDIM; c0 += 32) {
        // A tile [64 o x 32 c] -> As[c][o] (pitch 68), float4 along c
#pragma unroll
        for (int r = 0; r < 4; r++) {
            int e = t + r * 128;            // 0..511 float4 units
            int o_l = e >> 3;
            int c_l = (e & 7) * 4;
            int o = o0 + o_l;
            const float* src = (o < 1536) ? (w_qkv + (size_t)o * CDIM + c0 + c_l)
                                          : (w_g1 + (size_t)(o - 1536) * CDIM + c0 + c_l);
            float4 v4 = *(const float4*)src;
            As[(c_l + 0) * 68 + o_l] = v4.x;
            As[(c_l + 1) * 68 + o_l] = v4.y;
            As[(c_l + 2) * 68 + o_l] = v4.z;
            As[(c_l + 3) * 68 + o_l] = v4.w;
        }
        // B tile [32 c x 64 n], float4 along n
#pragma unroll
        for (int r = 0; r < 4; r++) {
            int e = t + r * 128;            // 0..511 float4 units
            int c_l = e >> 4;
            int n_l = (e & 15) * 4;
            *(float4*)(Bs + c_l * 64 + n_l) =
                *(const float4*)(xb + (size_t)(c0 + c_l) * NPIX + n0 + n_l);
        }
        __syncthreads();
#pragma unroll
        for (int cc = 0; cc < 32; cc++) {
            ull a[4], bb[4];
#pragma unroll
            for (int i = 0; i < 4; i++) a[i] = dup2(As[cc * 68 + to + i]);
            const ull* bp = (const ull*)(Bs + cc * 64 + tn);
#pragma unroll
            for (int p = 0; p < 4; p++) bb[p] = bp[p];
#pragma unroll
            for (int i = 0; i < 4; i++)
#pragma unroll
                for (int p = 0; p < 4; p++) acc[i][p] = fma2(a[i], bb[p], acc[i][p]);
        }
        __syncthreads();
    }

#pragma unroll
    for (int i = 0; i < 4; i++) {
        int o = o0 + to + i;
#pragma unroll
        for (int p = 0; p < 4; p++) {
            int n = n0 + tn + 2 * p;
            float v0 = lo2(acc[i][p]);
            float v1 = hi2(acc[i][p]);
            if (o < 512) {
                int h = o >> 6, d = o & 63;
                float* dst = g_q + (((size_t)(b * HEADS + h)) * DHEAD + d) * NPIX + n;
                dst[0] = v0; dst[1] = v1;
            } else if (o < 1024) {
                int oo = o - 512; int h = oo >> 6, d = oo & 63;
                float* dst = g_k + (((size_t)(b * HEADS + h)) * DHEAD + d) * NPIX + n;
                dst[0] = v0; dst[1] = v1;
            } else if (o < 1536) {
                int oo = o - 1024; int h = oo >> 6, d = oo & 63;
                float* dst = g_v + (((size_t)(b * HEADS + h)) * NPIX + n) * DHEAD + d;
                dst[0] = v0; dst[DHEAD] = v1;
            } else {
                int oo = o - 1536;
                float bg = b_g1[oo];
                float* dst = g_g1 + ((size_t)b * NPIX + n) * GDIM + oo;
                dst[0] = v0 + bg; dst[GDIM] = v1 + bg;
            }
        }
    }
}

// =====================================================================
// Kernel 2: gate second conv -> sigmoid -> dynamic k. (unchanged)
// =====================================================================
__global__ void __launch_bounds__(128) k_gate(const float* __restrict__ w_g2,
                                              const float* __restrict__ b_g2)
{
    int p = blockIdx.x * 4 + (threadIdx.x >> 5);
    int lane = threadIdx.x & 31;
    const float* g = g_g1 + (size_t)p * GDIM;
    float acc = 0.f;
#pragma unroll
    for (int r = 0; r < 4; r++) {
        int o = lane + r * 32;
        float gv = g[o];
        gv = gv > 0.f ? gv : 0.f;
        acc += gv * w_g2[o];
    }
#pragma unroll
    for (int s = 16; s; s >>= 1) acc += __shfl_xor_sync(0xffffffffu, acc, s);
    if (lane == 0) {
        float tau = 1.f / (1.f + expf(-(acc + b_g2[0])));
        int kd = (int)(tau * 32.f);
        kd = kd < 4 ? 4 : (kd > 32 ? 32 : kd);
        g_kdyn[p] = kd;
    }
}

// =====================================================================
// Kernel 3: fused sim GEMM + streaming top-32 + masked softmax + gather.
// Top-k: EXACT R2 logic (single min-heap per query, 64 owner threads,
// int indices, stride 64) -- the only structure that has passed.
// Perf changes vs R2 (math-identical): 256 threads; 128-wide key tiles
// (32 sync periods instead of 64); float4 tile loads; pitch-129 sim.
// grid: (NPIX/64 query tiles, B*HEADS), 256 threads.
// =====================================================================
#define SMEM_ATTN 98816

__global__ void __launch_bounds__(256) k_attn()
{
    extern __shared__ __align__(16) float sm[];
    float* qs  = sm;                   // [64 d][64 q]         @0
    float* ks  = qs + 4096;           // [64 d][128 j]        @4096
    float* sim = ks + 8192;           // [64 q][129]          @12288
    float* hv  = sim + 8256;          // [32][64] heap vals   @20544
    int*   hid = (int*)(hv + 2048);   // [32][64] heap idx    @22592
    int*   kds = hid + 2048;          // [64]                 @24640
    // reuse after phases end:
    float* sel_w = qs;                // [64][32]
    int*   sel_i = (int*)ks;          // [64][32]
    float* outs  = sim;               // [64 d][129]

    const int bh = blockIdx.y;
    const int b  = bh >> 3;
    const int h  = bh & 7;
    const int q0 = blockIdx.x * 64;
    const int t  = threadIdx.x;

    const float* qg = g_q + (size_t)bh * DHEAD * NPIX;
    const float* kg = g_k + (size_t)bh * DHEAD * NPIX;
    const float* vg = g_v + (size_t)bh * NPIX * DHEAD;

    // load q tile [64 d][64 q] (float4), init heaps, load k_dyn
    for (int e = t; e < 1024; e += 256) {
        int d = e >> 4, i4 = (e & 15) * 4;
        *(float4*)(qs + d * 64 + i4) = *(const float4*)(qg + (size_t)d * NPIX + q0 + i4);
    }
    for (int e = t; e < 2048; e += 256) { hv[e] = NEG_INF; hid[e] = 0; }
    if (t < 64) kds[t] = g_kdyn[b * NPIX + q0 + t];
    __syncthreads();

    const int tq = (t >> 4) * 4;      // 4 query rows per thread
    const int tj = (t & 15) * 8;      // 8 key cols per thread (within 128)

    for (int jt = 0; jt < 32; jt++) {
        // load k tile [64 d][128 j] (float4)
        for (int e = t; e < 2048; e += 256) {
            int d = e >> 5, j4 = (e & 31) * 4;
            *(float4*)(ks + d * 128 + j4) =
                *(const float4*)(kg + (size_t)d * NPIX + jt * 128 + j4);
        }
        __syncthreads();

        // 64x128 sim tile via f32x2 (per-(q,j) accumulation order == R2)
        ull acc[4][4];
#pragma unroll
        for (int i = 0; i < 4; i++)
#pragma unroll
            for (int p = 0; p < 4; p++) acc[i][p] = 0ULL;
#pragma unroll 4
        for (int dd = 0; dd < 64; dd++) {
            ull a[4], bb[4];
#pragma unroll
            for (int i = 0; i < 4; i++) a[i] = dup2(qs[dd * 64 + tq + i]);
            const ull* bp = (const ull*)(ks + dd * 128 + tj);
#pragma unroll
            for (int p = 0; p < 4; p++) bb[p] = bp[p];
#pragma unroll
            for (int i = 0; i < 4; i++)
#pragma unroll
                for (int p = 0; p < 4; p++) acc[i][p] = fma2(a[i], bb[p], acc[i][p]);
        }
#pragma unroll
        for (int i = 0; i < 4; i++)
#pragma unroll
            for (int p = 0; p < 4; p++) {
                sim[(tq + i) * 129 + tj + 2 * p]     = lo2(acc[i][p]) * 0.125f;
                sim[(tq + i) * 129 + tj + 2 * p + 1] = hi2(acc[i][p]) * 0.125f;
            }
        __syncthreads();

        // streaming top-32: owner thread per query (EXACT R2 logic),
        // scanning 128 keys in increasing index order
        if (t < 64) {
            const int q = t;
            const int jbase = jt * 128;
            float rootv = hv[q];
#pragma unroll 8
            for (int j = 0; j < 128; j++) {
                float val = sim[q * 129 + j];
                if (val > rootv) {       // strict: earliest index kept on ties
                    float cv = val; int ci = jbase + j;
                    int s = 0;
                    while (true) {
                        int l = 2 * s + 1, r = 2 * s + 2;
                        int m = s; float mv = cv;
                        if (l < 32) { float lv = hv[l * 64 + q]; if (lv < mv) { m = l; mv = lv; } }
                        if (r < 32) { float rv = hv[r * 64 + q]; if (rv < mv) { m = r; mv = rv; } }
                        if (m == s) break;
                        hv[s * 64 + q]  = mv;
                        hid[s * 64 + q] = hid[m * 64 + q];
                        s = m;
                    }
                    hv[s * 64 + q] = cv; hid[s * 64 + q] = ci;
                    rootv = hv[q];
                }
            }
        }
        __syncthreads();
    }

    // sort heap descending, apply k_dyn mask + softmax (EXACT R2 logic)
    if (t < 64) {
        const int q = t;
        for (int i = 1; i < 32; i++) {
            float kv = hv[i * 64 + q]; int ki = hid[i * 64 + q];
            int j = i - 1;
            while (j >= 0 && hv[j * 64 + q] < kv) {
                hv[(j + 1) * 64 + q]  = hv[j * 64 + q];
                hid[(j + 1) * 64 + q] = hid[j * 64 + q];
                j--;
            }
            hv[(j + 1) * 64 + q] = kv; hid[(j + 1) * 64 + q] = ki;
        }
        int kd = kds[q];
        float m = hv[q];                     // max
        float sum = 0.f;
        for (int s = 0; s < 32; s++) {
            float e = (s < kd) ? expf(hv[s * 64 + q] - m) : 0.f;
            sel_w[q * 32 + s] = e;
            sum += e;
        }
        float inv = 1.f / sum;
        for (int s = 0; s < 32; s++) {
            sel_w[q * 32 + s] *= inv;
            sel_i[q * 32 + s] = hid[s * 64 + q];
        }
    }
    __syncthreads();

    // weighted v gather: thread -> (q, 16-d quarter), all 256 threads
    {
        const int q  = t >> 2;
        const int dq = (t & 3) * 16;
        float acc[16];
#pragma unroll
        for (int u = 0; u < 16; u++) acc[u] = 0.f;
#pragma unroll 4
        for (int s = 0; s < 32; s++) {
            float w  = sel_w[q * 32 + s];
            int  idx = sel_i[q * 32 + s];
            const float4* vr = (const float4*)(vg + (size_t)idx * DHEAD + dq);
#pragma unroll
            for (int u = 0; u < 4; u++) {
                float4 vv = vr[u];
                acc[u * 4 + 0] += w * vv.x;
                acc[u * 4 + 1] += w * vv.y;
                acc[u * 4 + 2] += w * vv.z;
                acc[u * 4 + 3] += w * vv.w;
            }
        }
#pragma unroll
        for (int u = 0; u < 16; u++)
            outs[(dq + u) * 129 + q] = acc[u];
    }
    __syncthreads();

    // coalesced write: g_attn[b][h*64+d][q0+q]
    float* ab = g_attn + ((size_t)(b * CDIM + h * DHEAD)) * NPIX + q0;
    for (int e = t; e < 4096; e += 256) {
        int d = e >> 6, qq = e & 63;
        ab[(size_t)d * NPIX + qq] = outs[d * 129 + qq];
    }
}

// =====================================================================
// Kernel 4: proj conv + bias + residual. k-tile 32 + float4 B loads.
// =====================================================================
__global__ void __launch_bounds__(128) k_proj(const float* __restrict__ x,
                                              const float* __restrict__ w_proj,
                                              const float* __restrict__ b_proj,
                                              float* __restrict__ out)
{
    __shared__ __align__(16) float As[32 * 68];
    __shared__ __align__(16) float Bs[32 * 64];
    const int b  = blockIdx.z;
    const int o0 = blockIdx.y * 64;
    const int n0 = blockIdx.x * 64;
    const int t  = threadIdx.x;
    const int to = (t >> 3) * 4;
    const int tn = (t & 7) * 8;
    const float* ab = g_attn + (size_t)b * CDIM * NPIX;

    ull acc[4][4];
#pragma unroll
    for (int i = 0; i < 4; i++)
#pragma unroll
        for (int p = 0; p < 4; p++) acc[i][p] = 0ULL;

    for (int c0 = 0; c0 < CDIM; c0 += 32) {
#pragma unroll
        for (int r = 0; r < 4; r++) {
            int e = t + r * 128;
            int o_l = e >> 3;
            int c_l = (e & 7) * 4;
            float4 v4 = *(const float4*)(w_proj + (size_t)(o0 + o_l) * CDIM + c0 + c_l);
            As[(c_l + 0) * 68 + o_l] = v4.x;
            As[(c_l + 1) * 68 + o_l] = v4.y;
            As[(c_l + 2) * 68 + o_l] = v4.z;
            As[(c_l + 3) * 68 + o_l] = v4.w;
        }
#pragma unroll
        for (int r = 0; r < 4; r++) {
            int e = t + r * 128;
            int c_l = e >> 4;
            int n_l = (e & 15) * 4;
            *(float4*)(Bs + c_l * 64 + n_l) =
                *(const float4*)(ab + (size_t)(c0 + c_l) * NPIX + n0 + n_l);
        }
        __syncthreads();
#pragma unroll
        for (int cc = 0; cc < 32; cc++) {
            ull a[4], bb[4];
#pragma unroll
            for (int i = 0; i < 4; i++) a[i] = dup2(As[cc * 68 + to + i]);
            const ull* bp = (const ull*)(Bs + cc * 64 + tn);
#pragma unroll
            for (int p = 0; p < 4; p++) bb[p] = bp[p];
#pragma unroll
            for (int i = 0; i < 4; i++)
#pragma unroll
                for (int p = 0; p < 4; p++) acc[i][p] = fma2(a[i], bb[p], acc[i][p]);
        }
        __syncthreads();
    }

#pragma unroll
    for (int i = 0; i < 4; i++) {
        int o = o0 + to + i;
        float bp0 = b_proj[o];
#pragma unroll
        for (int p = 0; p < 4; p++) {
            int n = n0 + tn + 2 * p;
            size_t base = ((size_t)b * CDIM + o) * NPIX + n;
            out[base]     = lo2(acc[i][p]) + bp0 + x[base];
            out[base + 1] = hi2(acc[i][p]) + bp0 + x[base + 1];
        }
    }
}

// =====================================================================
extern "C" void kernel_launch(void* const* d_in, const int* in_sizes, int n_in,
                              void* d_out, int out_size)
{
    const float* x      = (const float*)d_in[0];
    const float* w_qkv  = (const float*)d_in[1];
    const float* w_proj = (const float*)d_in[2];
    const float* b_proj = (const float*)d_in[3];
    const float* w_g1   = (const float*)d_in[4];
    const float* b_g1   = (const float*)d_in[5];
    const float* w_g2   = (const float*)d_in[6];
    const float* b_g2   = (const float*)d_in[7];
    float* out = (float*)d_out;

    cudaFuncSetAttribute(k_attn, cudaFuncAttributeMaxDynamicSharedMemorySize, SMEM_ATTN);

    k_qkv<<<dim3(NPIX / 64, 26, BATCH), 128>>>(x, w_qkv, w_g1, b_g1);
    k_gate<<<(BATCH * NPIX) / 4, 128>>>(w_g2, b_g2);
    k_attn<<<dim3(NPIX / 64, BATCH * HEADS), 256, SMEM_ATTN>>>();
    k_proj<<<dim3(NPIX / 64, CDIM / 64, BATCH), 128>>>(x, w_proj, b_proj, out);
}

// round 10
// speedup vs baseline: 1.4237x; 1.4237x over previous
#include <cuda_runtime.h>
#include <math.h>

#define BATCH 2
#define CDIM  512
#define HEADS 8
#define DHEAD 64
#define NPIX  4096
#define KTOP  32
#define GDIM  128

typedef unsigned long long ull;
typedef unsigned int uint32;

#define NEG_INF (__int_as_float(0xff800000))

// ---------------- scratch (device globals; no allocation allowed) ----------------
__device__ float g_q[BATCH*HEADS*DHEAD*NPIX];   // [b][h][d][n]
__device__ float g_k[BATCH*HEADS*DHEAD*NPIX];   // [b][h][d][n]
__device__ float g_v[BATCH*HEADS*NPIX*DHEAD];   // [b][h][n][d]
__device__ float g_g1[BATCH*NPIX*GDIM];         // [b][n][o]  gate hidden (bias applied)
__device__ float g_attn[BATCH*CDIM*NPIX];       // [b][c][n]  attention output (pre-proj)
__device__ int   g_kdyn[BATCH*NPIX];
__device__ float g_sim[(size_t)BATCH*HEADS*NPIX*NPIX];  // [bh][q][j]  1.07 GB

// ---------------- f32x2 helpers (sm_103a packed fp32) ----------------
__device__ __forceinline__ ull fma2(ull a, ull b, ull c) {
    ull d;
    asm("fma.rn.f32x2 %0, %1, %2, %3;" : "=l"(d) : "l"(a), "l"(b), "l"(c));
    return d;
}
__device__ __forceinline__ ull dup2(float x) {
    ull r; unsigned u = __float_as_uint(x);
    asm("mov.b64 %0, {%1, %1};" : "=l"(r) : "r"(u));
    return r;
}
__device__ __forceinline__ float lo2(ull x) { return __uint_as_float((unsigned)x); }
__device__ __forceinline__ float hi2(ull x) { return __uint_as_float((unsigned)(x >> 32)); }

// =====================================================================
// Kernel 1: fused qkv conv (1536 rows) + gate conv1 (128 rows) GEMM.
// (unchanged from passing R7 kernel)
// =====================================================================
__global__ void __launch_bounds__(128) k_qkv(const float* __restrict__ x,
                                             const float* __restrict__ w_qkv,
                                             const float* __restrict__ w_g1,
                                             const float* __restrict__ b_g1)
{
    __shared__ __align__(16) float As[32 * 68];
    __shared__ __align__(16) float Bs[32 * 64];
    const int b  = blockIdx.z;
    const int o0 = blockIdx.y * 64;
    const int n0 = blockIdx.x * 64;
    const int t  = threadIdx.x;
    const int to = (t >> 3) * 4;
    const int tn = (t & 7) * 8;
    const float* xb = x + (size_t)b * CDIM * NPIX;

    ull acc[4][4];
#pragma unroll
    for (int i = 0; i < 4; i++)
#pragma unroll
        for (int p = 0; p < 4; p++) acc[i][p] = 0ULL;

    for (int c0 = 0; c0 < CDIM; c0 += 32) {
#pragma unroll
        for (int r = 0; r < 4; r++) {
            int e = t + r * 128;
            int o_l = e >> 3;
            int c_l = (e & 7) * 4;
            int o = o0 + o_l;
            const float* src = (o < 1536) ? (w_qkv + (size_t)o * CDIM + c0 + c_l)
                                          : (w_g1 + (size_t)(o - 1536) * CDIM + c0 + c_l);
            float4 v4 = *(const float4*)src;
            As[(c_l + 0) * 68 + o_l] = v4.x;
            As[(c_l + 1) * 68 + o_l] = v4.y;
            As[(c_l + 2) * 68 + o_l] = v4.z;
            As[(c_l + 3) * 68 + o_l] = v4.w;
        }
#pragma unroll
        for (int r = 0; r < 4; r++) {
            int e = t + r * 128;
            int c_l = e >> 4;
            int n_l = (e & 15) * 4;
            *(float4*)(Bs + c_l * 64 + n_l) =
                *(const float4*)(xb + (size_t)(c0 + c_l) * NPIX + n0 + n_l);
        }
        __syncthreads();
#pragma unroll
        for (int cc = 0; cc < 32; cc++) {
            ull a[4], bb[4];
#pragma unroll
            for (int i = 0; i < 4; i++) a[i] = dup2(As[cc * 68 + to + i]);
            const ull* bp = (const ull*)(Bs + cc * 64 + tn);
#pragma unroll
            for (int p = 0; p < 4; p++) bb[p] = bp[p];
#pragma unroll
            for (int i = 0; i < 4; i++)
#pragma unroll
                for (int p = 0; p < 4; p++) acc[i][p] = fma2(a[i], bb[p], acc[i][p]);
        }
        __syncthreads();
    }

#pragma unroll
    for (int i = 0; i < 4; i++) {
        int o = o0 + to + i;
#pragma unroll
        for (int p = 0; p < 4; p++) {
            int n = n0 + tn + 2 * p;
            float v0 = lo2(acc[i][p]);
            float v1 = hi2(acc[i][p]);
            if (o < 512) {
                int h = o >> 6, d = o & 63;
                float* dst = g_q + (((size_t)(b * HEADS + h)) * DHEAD + d) * NPIX + n;
                dst[0] = v0; dst[1] = v1;
            } else if (o < 1024) {
                int oo = o - 512; int h = oo >> 6, d = oo & 63;
                float* dst = g_k + (((size_t)(b * HEADS + h)) * DHEAD + d) * NPIX + n;
                dst[0] = v0; dst[1] = v1;
            } else if (o < 1536) {
                int oo = o - 1024; int h = oo >> 6, d = oo & 63;
                float* dst = g_v + (((size_t)(b * HEADS + h)) * NPIX + n) * DHEAD + d;
                dst[0] = v0; dst[DHEAD] = v1;
            } else {
                int oo = o - 1536;
                float bg = b_g1[oo];
                float* dst = g_g1 + ((size_t)b * NPIX + n) * GDIM + oo;
                dst[0] = v0 + bg; dst[GDIM] = v1 + bg;
            }
        }
    }
}

// =====================================================================
// Kernel 2: gate second conv -> sigmoid -> dynamic k. (unchanged)
// =====================================================================
__global__ void __launch_bounds__(128) k_gate(const float* __restrict__ w_g2,
                                              const float* __restrict__ b_g2)
{
    int p = blockIdx.x * 4 + (threadIdx.x >> 5);
    int lane = threadIdx.x & 31;
    const float* g = g_g1 + (size_t)p * GDIM;
    float acc = 0.f;
#pragma unroll
    for (int r = 0; r < 4; r++) {
        int o = lane + r * 32;
        float gv = g[o];
        gv = gv > 0.f ? gv : 0.f;
        acc += gv * w_g2[o];
    }
#pragma unroll
    for (int s = 16; s; s >>= 1) acc += __shfl_xor_sync(0xffffffffu, acc, s);
    if (lane == 0) {
        float tau = 1.f / (1.f + expf(-(acc + b_g2[0])));
        int kd = (int)(tau * 32.f);
        kd = kd < 4 ? 4 : (kd > 32 ? 32 : kd);
        g_kdyn[p] = kd;
    }
}

// =====================================================================
// Kernel 3a: sim GEMM -> global (values bit-identical to R7's sim tile).
// grid (NPIX/64 qtiles, B*HEADS), 256 threads, 64x128 tiles, 32 j-tiles.
// =====================================================================
__global__ void __launch_bounds__(256) k_sim()
{
    __shared__ __align__(16) float qs[4096];   // [64 d][64 q]
    __shared__ __align__(16) float ks[8192];   // [64 d][128 j]

    const int bh = blockIdx.y;
    const int q0 = blockIdx.x * 64;
    const int t  = threadIdx.x;

    const float* qg = g_q + (size_t)bh * DHEAD * NPIX;
    const float* kg = g_k + (size_t)bh * DHEAD * NPIX;

    for (int e = t; e < 1024; e += 256) {
        int d = e >> 4, i4 = (e & 15) * 4;
        *(float4*)(qs + d * 64 + i4) = *(const float4*)(qg + (size_t)d * NPIX + q0 + i4);
    }
    __syncthreads();

    const int tq = (t >> 4) * 4;
    const int tj = (t & 15) * 8;

    for (int jt = 0; jt < 32; jt++) {
        for (int e = t; e < 2048; e += 256) {
            int d = e >> 5, j4 = (e & 31) * 4;
            *(float4*)(ks + d * 128 + j4) =
                *(const float4*)(kg + (size_t)d * NPIX + jt * 128 + j4);
        }
        __syncthreads();

        ull acc[4][4];
#pragma unroll
        for (int i = 0; i < 4; i++)
#pragma unroll
            for (int p = 0; p < 4; p++) acc[i][p] = 0ULL;
#pragma unroll 4
        for (int dd = 0; dd < 64; dd++) {
            ull a[4], bb[4];
#pragma unroll
            for (int i = 0; i < 4; i++) a[i] = dup2(qs[dd * 64 + tq + i]);
            const ull* bp = (const ull*)(ks + dd * 128 + tj);
#pragma unroll
            for (int p = 0; p < 4; p++) bb[p] = bp[p];
#pragma unroll
            for (int i = 0; i < 4; i++)
#pragma unroll
                for (int p = 0; p < 4; p++) acc[i][p] = fma2(a[i], bb[p], acc[i][p]);
        }

#pragma unroll
        for (int i = 0; i < 4; i++) {
            float* srow = g_sim + ((size_t)bh * NPIX + q0 + tq + i) * NPIX + jt * 128 + tj;
#pragma unroll
            for (int p = 0; p < 4; p++) {
                float2 st = make_float2(lo2(acc[i][p]) * 0.125f, hi2(acc[i][p]) * 0.125f);
                *(float2*)(srow + 2 * p) = st;
            }
        }
        __syncthreads();
    }
}

// =====================================================================
// Kernel 3b: exact per-query top-32 (radix select on monotonic uint) +
//            kd-mask softmax + weighted v gather + coalesced output.
// grid (NPIX/64 qtiles, B*HEADS), 256 threads; queries processed
// sequentially, each phase block-cooperative and branch-uniform.
// =====================================================================
__global__ void __launch_bounds__(256) k_select()
{
    __shared__ uint32 hist[256];
    __shared__ uint32 svals[32];
    __shared__ int    sidx[32];
    __shared__ float  sortv[32];
    __shared__ int    sorti[32];
    __shared__ float  wsel[32];
    __shared__ int    kds[64];
    __shared__ float  outs[64 * 65];
    __shared__ uint32 bin_s, before_s;
    __shared__ int    cnt_s, gmin_s;

    const int bh = blockIdx.y;
    const int b  = bh >> 3;
    const int h  = bh & 7;
    const int q0 = blockIdx.x * 64;
    const int t  = threadIdx.x;
    const int lane = t & 31;

    const float* vg = g_v + (size_t)bh * NPIX * DHEAD;

    if (t < 64) kds[t] = g_kdyn[b * NPIX + q0 + t];
    __syncthreads();

    for (int q = 0; q < 64; q++) {
        const uint32* row = (const uint32*)g_sim + ((size_t)bh * NPIX + q0 + q) * NPIX;
        const int base = t * 16;
        uint32 vals[16];
#pragma unroll
        for (int u = 0; u < 4; u++) {
            uint4 w = *(const uint4*)(row + base + u * 4);
            vals[u * 4 + 0] = w.x; vals[u * 4 + 1] = w.y;
            vals[u * 4 + 2] = w.z; vals[u * 4 + 3] = w.w;
        }
        // monotonic transform: unsigned ascending == float ascending
#pragma unroll
        for (int i = 0; i < 16; i++) {
            uint32 u = vals[i];
            vals[i] = (u & 0x80000000u) ? ~u : (u | 0x80000000u);
        }

        uint32 prefix = 0;
        int remaining = 32;     // rank we still need within the candidate set
#pragma unroll
        for (int lvl = 0; lvl < 4; lvl++) {
            const int sh = 24 - lvl * 8;
            const uint32 hiMask = (lvl == 0) ? 0u : (0xFFFFFFFFu << (32 - 8 * lvl));
            hist[t] = 0;
            __syncthreads();
#pragma unroll
            for (int i = 0; i < 16; i++) {
                uint32 v = vals[i];
                if ((v & hiMask) == prefix) atomicAdd(&hist[(v >> sh) & 0xFF], 1u);
            }
            __syncthreads();
            if (t < 32) {
                const int lo = 248 - t * 8;   // lane 0 owns top bins 248..255
                uint32 c[8]; uint32 csum = 0;
#pragma unroll
                for (int j = 0; j < 8; j++) { c[j] = hist[lo + j]; csum += c[j]; }
                uint32 inc = csum;
#pragma unroll
                for (int o = 1; o < 32; o <<= 1) {
                    uint32 x = __shfl_up_sync(0xffffffffu, inc, o);
                    if (t >= o) inc += x;
                }
                uint32 pre = inc - csum;      // count in strictly higher chunks
                if (pre < (uint32)remaining && inc >= (uint32)remaining) {
                    uint32 acc = pre; int sel = -1; uint32 before = 0;
#pragma unroll
                    for (int j = 7; j >= 0; j--) {
                        acc += c[j];
                        if (sel < 0 && acc >= (uint32)remaining) { sel = lo + j; before = acc - c[j]; }
                    }
                    bin_s = (uint32)sel; before_s = before;
                }
            }
            __syncthreads();
            prefix |= (bin_s << sh);
            remaining -= (int)before_s;
            __syncthreads();                  // protect bin_s/before_s for next level
        }
        const uint32 pivot = prefix;          // exact 32-bit key of the 32nd largest
        const int need = remaining;           // # pivot-equal entries to take (>=1)

        if (t == 0) cnt_s = 0;
        __syncthreads();
#pragma unroll
        for (int i = 0; i < 16; i++) {
            uint32 v = vals[i];
            if (v > pivot) { int p = atomicAdd(&cnt_s, 1); svals[p] = v; sidx[p] = base + i; }
        }
        __syncthreads();
        const int cg = cnt_s;                 // == 32 - need

        // pivot-equal entries: take the `need` smallest indices (lax.top_k tiebreak)
        int prevIdx = -1;
        for (int r = 0; r < need; r++) {
            if (t == 0) gmin_s = 0x7fffffff;
            __syncthreads();
            int best = 0x7fffffff;
#pragma unroll
            for (int i = 0; i < 16; i++) {
                if (vals[i] == pivot && (base + i) > prevIdx) { best = base + i; break; }
            }
            if (best != 0x7fffffff) atomicMin(&gmin_s, best);
            __syncthreads();
            int winner = gmin_s;
            if (t == 0) { svals[cg + r] = pivot; sidx[cg + r] = winner; }
            prevIdx = winner;
            __syncthreads();
        }

        // rank-sort the 32 selected (value desc, index asc) — exact permutation
        if (t < 32) {
            uint32 vi = svals[t]; int ii = sidx[t];
            int rank = 0;
#pragma unroll
            for (int j = 0; j < 32; j++) {
                uint32 vj = svals[j]; int ij = sidx[j];
                rank += (vj > vi) || (vj == vi && ij < ii);
            }
            uint32 fb = (vi & 0x80000000u) ? (vi ^ 0x80000000u) : ~vi;  // inverse transform
            sortv[rank] = __uint_as_float(fb);
            sorti[rank] = ii;
        }
        __syncthreads();

        // kd-mask softmax (warp 0)
        if (t < 32) {
            int kd = kds[q];
            float m = sortv[0];
            float e = (t < kd) ? expf(sortv[t] - m) : 0.f;
            float s = e;
#pragma unroll
            for (int o = 16; o; o >>= 1) s += __shfl_xor_sync(0xffffffffu, s, o);
            wsel[t] = e / s;
        }
        __syncthreads();

        // weighted v gather: 64 threads, one output dim each (coalesced v rows)
        if (t < 64) {
            float acc = 0.f;
#pragma unroll 4
            for (int s = 0; s < 32; s++)
                acc += wsel[s] * vg[(size_t)sorti[s] * DHEAD + t];
            outs[t * 65 + q] = acc;
        }
        __syncthreads();
    }

    // coalesced write: g_attn[b][h*64+d][q0+q]
    float* ab = g_attn + ((size_t)(b * CDIM + h * DHEAD)) * NPIX + q0;
    for (int e = t; e < 4096; e += 256) {
        int d = e >> 6, qq = e & 63;
        ab[(size_t)d * NPIX + qq] = outs[d * 65 + qq];
    }
}

// =====================================================================
// Kernel 4: proj conv + bias + residual. (unchanged from R7)
// =====================================================================
__global__ void __launch_bounds__(128) k_proj(const float* __restrict__ x,
                                              const float* __restrict__ w_proj,
                                              const float* __restrict__ b_proj,
                                              float* __restrict__ out)
{
    __shared__ __align__(16) float As[32 * 68];
    __shared__ __align__(16) float Bs[32 * 64];
    const int b  = blockIdx.z;
    const int o0 = blockIdx.y * 64;
    const int n0 = blockIdx.x * 64;
    const int t  = threadIdx.x;
    const int to = (t >> 3) * 4;
    const int tn = (t & 7) * 8;
    const float* ab = g_attn + (size_t)b * CDIM * NPIX;

    ull acc[4][4];
#pragma unroll
    for (int i = 0; i < 4; i++)
#pragma unroll
        for (int p = 0; p < 4; p++) acc[i][p] = 0ULL;

    for (int c0 = 0; c0 < CDIM; c0 += 32) {
#pragma unroll
        for (int r = 0; r < 4; r++) {
            int e = t + r * 128;
            int o_l = e >> 3;
            int c_l = (e & 7) * 4;
            float4 v4 = *(const float4*)(w_proj + (size_t)(o0 + o_l) * CDIM + c0 + c_l);
            As[(c_l + 0) * 68 + o_l] = v4.x;
            As[(c_l + 1) * 68 + o_l] = v4.y;
            As[(c_l + 2) * 68 + o_l] = v4.z;
            As[(c_l + 3) * 68 + o_l] = v4.w;
        }
#pragma unroll
        for (int r = 0; r < 4; r++) {
            int e = t + r * 128;
            int c_l = e >> 4;
            int n_l = (e & 15) * 4;
            *(float4*)(Bs + c_l * 64 + n_l) =
                *(const float4*)(ab + (size_t)(c0 + c_l) * NPIX + n0 + n_l);
        }
        __syncthreads();
#pragma unroll
        for (int cc = 0; cc < 32; cc++) {
            ull a[4], bb[4];
#pragma unroll
            for (int i = 0; i < 4; i++) a[i] = dup2(As[cc * 68 + to + i]);
            const ull* bp = (const ull*)(Bs + cc * 64 + tn);
#pragma unroll
            for (int p = 0; p < 4; p++) bb[p] = bp[p];
#pragma unroll
            for (int i = 0; i < 4; i++)
#pragma unroll
                for (int p = 0; p < 4; p++) acc[i][p] = fma2(a[i], bb[p], acc[i][p]);
        }
        __syncthreads();
    }

#pragma unroll
    for (int i = 0; i < 4; i++) {
        int o = o0 + to + i;
        float bp0 = b_proj[o];
#pragma unroll
        for (int p = 0; p < 4; p++) {
            int n = n0 + tn + 2 * p;
            size_t base = ((size_t)b * CDIM + o) * NPIX + n;
            out[base]     = lo2(acc[i][p]) + bp0 + x[base];
            out[base + 1] = hi2(acc[i][p]) + bp0 + x[base + 1];
        }
    }
}

// =====================================================================
extern "C" void kernel_launch(void* const* d_in, const int* in_sizes, int n_in,
                              void* d_out, int out_size)
{
    const float* x      = (const float*)d_in[0];
    const float* w_qkv  = (const float*)d_in[1];
    const float* w_proj = (const float*)d_in[2];
    const float* b_proj = (const float*)d_in[3];
    const float* w_g1   = (const float*)d_in[4];
    const float* b_g1   = (const float*)d_in[5];
    const float* w_g2   = (const float*)d_in[6];
    const float* b_g2   = (const float*)d_in[7];
    float* out = (float*)d_out;

    k_qkv<<<dim3(NPIX / 64, 26, BATCH), 128>>>(x, w_qkv, w_g1, b_g1);
    k_gate<<<(BATCH * NPIX) / 4, 128>>>(w_g2, b_g2);
    k_sim<<<dim3(NPIX / 64, BATCH * HEADS), 256>>>();
    k_select<<<dim3(NPIX / 64, BATCH * HEADS), 256>>>();
    k_proj<<<dim3(NPIX / 64, CDIM / 64, BATCH), 128>>>(x, w_proj, b_proj, out);
}

// round 11
// speedup vs baseline: 1.4251x; 1.0010x over previous
#include <cuda_runtime.h>
#include <math.h>

#define BATCH 2
#define CDIM  512
#define HEADS 8
#define DHEAD 64
#define NPIX  4096
#define KTOP  32
#define GDIM  128

typedef unsigned long long ull;
typedef unsigned int uint32;

#define NEG_INF (__int_as_float(0xff800000))

// ---------------- scratch (device globals; no allocation allowed) ----------------
__device__ float g_q[BATCH*HEADS*DHEAD*NPIX];   // [b][h][d][n]
__device__ float g_k[BATCH*HEADS*DHEAD*NPIX];   // [b][h][d][n]
__device__ float g_v[BATCH*HEADS*NPIX*DHEAD];   // [b][h][n][d]
__device__ float g_g1[BATCH*NPIX*GDIM];         // [b][n][o]  gate hidden (bias applied)
__device__ float g_attn[BATCH*CDIM*NPIX];       // [b][c][n]  attention output (pre-proj)
__device__ int   g_kdyn[BATCH*NPIX];
__device__ float g_sim[(size_t)BATCH*HEADS*NPIX*NPIX];  // [bh][q][j]  1.07 GB

// ---------------- f32x2 helpers (sm_103a packed fp32) ----------------
__device__ __forceinline__ ull fma2(ull a, ull b, ull c) {
    ull d;
    asm("fma.rn.f32x2 %0, %1, %2, %3;" : "=l"(d) : "l"(a), "l"(b), "l"(c));
    return d;
}
__device__ __forceinline__ ull dup2(float x) {
    ull r; unsigned u = __float_as_uint(x);
    asm("mov.b64 %0, {%1, %1};" : "=l"(r) : "r"(u));
    return r;
}
__device__ __forceinline__ float lo2(ull x) { return __uint_as_float((unsigned)x); }
__device__ __forceinline__ float hi2(ull x) { return __uint_as_float((unsigned)(x >> 32)); }

// =====================================================================
// Kernel 1: fused qkv conv (1536 rows) + gate conv1 (128 rows) GEMM.
// (unchanged from passing R7 kernel)
// =====================================================================
__global__ void __launch_bounds__(128) k_qkv(const float* __restrict__ x,
                                             const float* __restrict__ w_qkv,
                                             const float* __restrict__ w_g1,
                                             const float* __restrict__ b_g1)
{
    __shared__ __align__(16) float As[32 * 68];
    __shared__ __align__(16) float Bs[32 * 64];
    const int b  = blockIdx.z;
    const int o0 = blockIdx.y * 64;
    const int n0 = blockIdx.x * 64;
    const int t  = threadIdx.x;
    const int to = (t >> 3) * 4;
    const int tn = (t & 7) * 8;
    const float* xb = x + (size_t)b * CDIM * NPIX;

    ull acc[4][4];
#pragma unroll
    for (int i = 0; i < 4; i++)
#pragma unroll
        for (int p = 0; p < 4; p++) acc[i][p] = 0ULL;

    for (int c0 = 0; c0 < CDIM; c0 += 32) {
#pragma unroll
        for (int r = 0; r < 4; r++) {
            int e = t + r * 128;
            int o_l = e >> 3;
            int c_l = (e & 7) * 4;
            int o = o0 + o_l;
            const float* src = (o < 1536) ? (w_qkv + (size_t)o * CDIM + c0 + c_l)
                                          : (w_g1 + (size_t)(o - 1536) * CDIM + c0 + c_l);
            float4 v4 = *(const float4*)src;
            As[(c_l + 0) * 68 + o_l] = v4.x;
            As[(c_l + 1) * 68 + o_l] = v4.y;
            As[(c_l + 2) * 68 + o_l] = v4.z;
            As[(c_l + 3) * 68 + o_l] = v4.w;
        }
#pragma unroll
        for (int r = 0; r < 4; r++) {
            int e = t + r * 128;
            int c_l = e >> 4;
            int n_l = (e & 15) * 4;
            *(float4*)(Bs + c_l * 64 + n_l) =
                *(const float4*)(xb + (size_t)(c0 + c_l) * NPIX + n0 + n_l);
        }
        __syncthreads();
#pragma unroll
        for (int cc = 0; cc < 32; cc++) {
            ull a[4], bb[4];
#pragma unroll
            for (int i = 0; i < 4; i++) a[i] = dup2(As[cc * 68 + to + i]);
            const ull* bp = (const ull*)(Bs + cc * 64 + tn);
#pragma unroll
            for (int p = 0; p < 4; p++) bb[p] = bp[p];
#pragma unroll
            for (int i = 0; i < 4; i++)
#pragma unroll
                for (int p = 0; p < 4; p++) acc[i][p] = fma2(a[i], bb[p], acc[i][p]);
        }
        __syncthreads();
    }

#pragma unroll
    for (int i = 0; i < 4; i++) {
        int o = o0 + to + i;
#pragma unroll
        for (int p = 0; p < 4; p++) {
            int n = n0 + tn + 2 * p;
            float v0 = lo2(acc[i][p]);
            float v1 = hi2(acc[i][p]);
            if (o < 512) {
                int h = o >> 6, d = o & 63;
                float* dst = g_q + (((size_t)(b * HEADS + h)) * DHEAD + d) * NPIX + n;
                dst[0] = v0; dst[1] = v1;
            } else if (o < 1024) {
                int oo = o - 512; int h = oo >> 6, d = oo & 63;
                float* dst = g_k + (((size_t)(b * HEADS + h)) * DHEAD + d) * NPIX + n;
                dst[0] = v0; dst[1] = v1;
            } else if (o < 1536) {
                int oo = o - 1024; int h = oo >> 6, d = oo & 63;
                float* dst = g_v + (((size_t)(b * HEADS + h)) * NPIX + n) * DHEAD + d;
                dst[0] = v0; dst[DHEAD] = v1;
            } else {
                int oo = o - 1536;
                float bg = b_g1[oo];
                float* dst = g_g1 + ((size_t)b * NPIX + n) * GDIM + oo;
                dst[0] = v0 + bg; dst[GDIM] = v1 + bg;
            }
        }
    }
}

// =====================================================================
// Kernel 2: gate second conv -> sigmoid -> dynamic k. (unchanged)
// =====================================================================
__global__ void __launch_bounds__(128) k_gate(const float* __restrict__ w_g2,
                                              const float* __restrict__ b_g2)
{
    int p = blockIdx.x * 4 + (threadIdx.x >> 5);
    int lane = threadIdx.x & 31;
    const float* g = g_g1 + (size_t)p * GDIM;
    float acc = 0.f;
#pragma unroll
    for (int r = 0; r < 4; r++) {
        int o = lane + r * 32;
        float gv = g[o];
        gv = gv > 0.f ? gv : 0.f;
        acc += gv * w_g2[o];
    }
#pragma unroll
    for (int s = 16; s; s >>= 1) acc += __shfl_xor_sync(0xffffffffu, acc, s);
    if (lane == 0) {
        float tau = 1.f / (1.f + expf(-(acc + b_g2[0])));
        int kd = (int)(tau * 32.f);
        kd = kd < 4 ? 4 : (kd > 32 ? 32 : kd);
        g_kdyn[p] = kd;
    }
}

// =====================================================================
// Kernel 3a: sim GEMM -> global (values bit-identical to R7's sim tile).
// grid (NPIX/64 qtiles, B*HEADS), 256 threads, 64x128 tiles, 32 j-tiles.
// =====================================================================
__global__ void __launch_bounds__(256) k_sim()
{
    __shared__ __align__(16) float qs[4096];   // [64 d][64 q]
    __shared__ __align__(16) float ks[8192];   // [64 d][128 j]

    const int bh = blockIdx.y;
    const int q0 = blockIdx.x * 64;
    const int t  = threadIdx.x;

    const float* qg = g_q + (size_t)bh * DHEAD * NPIX;
    const float* kg = g_k + (size_t)bh * DHEAD * NPIX;

    for (int e = t; e < 1024; e += 256) {
        int d = e >> 4, i4 = (e & 15) * 4;
        *(float4*)(qs + d * 64 + i4) = *(const float4*)(qg + (size_t)d * NPIX + q0 + i4);
    }
    __syncthreads();

    const int tq = (t >> 4) * 4;
    const int tj = (t & 15) * 8;

    for (int jt = 0; jt < 32; jt++) {
        for (int e = t; e < 2048; e += 256) {
            int d = e >> 5, j4 = (e & 31) * 4;
            *(float4*)(ks + d * 128 + j4) =
                *(const float4*)(kg + (size_t)d * NPIX + jt * 128 + j4);
        }
        __syncthreads();

        ull acc[4][4];
#pragma unroll
        for (int i = 0; i < 4; i++)
#pragma unroll
            for (int p = 0; p < 4; p++) acc[i][p] = 0ULL;
#pragma unroll 4
        for (int dd = 0; dd < 64; dd++) {
            ull a[4], bb[4];
#pragma unroll
            for (int i = 0; i < 4; i++) a[i] = dup2(qs[dd * 64 + tq + i]);
            const ull* bp = (const ull*)(ks + dd * 128 + tj);
#pragma unroll
            for (int p = 0; p < 4; p++) bb[p] = bp[p];
#pragma unroll
            for (int i = 0; i < 4; i++)
#pragma unroll
                for (int p = 0; p < 4; p++) acc[i][p] = fma2(a[i], bb[p], acc[i][p]);
        }

#pragma unroll
        for (int i = 0; i < 4; i++) {
            float* srow = g_sim + ((size_t)bh * NPIX + q0 + tq + i) * NPIX + jt * 128 + tj;
#pragma unroll
            for (int p = 0; p < 4; p++) {
                float2 st = make_float2(lo2(acc[i][p]) * 0.125f, hi2(acc[i][p]) * 0.125f);
                *(float2*)(srow + 2 * p) = st;
            }
        }
        __syncthreads();
    }
}

// =====================================================================
// Kernel 3b: exact per-query top-32 (radix select on monotonic uint) +
//            kd-mask softmax + weighted v gather + coalesced output.
// grid (NPIX/64 qtiles, B*HEADS), 256 threads; queries processed
// sequentially, each phase block-cooperative and branch-uniform.
// =====================================================================
__global__ void __launch_bounds__(256) k_select()
{
    __shared__ uint32 hist[256];
    __shared__ uint32 svals[32];
    __shared__ int    sidx[32];
    __shared__ float  sortv[32];
    __shared__ int    sorti[32];
    __shared__ float  wsel[32];
    __shared__ int    kds[64];
    __shared__ float  outs[64 * 65];
    __shared__ uint32 bin_s, before_s;
    __shared__ int    cnt_s, gmin_s;

    const int bh = blockIdx.y;
    const int b  = bh >> 3;
    const int h  = bh & 7;
    const int q0 = blockIdx.x * 64;
    const int t  = threadIdx.x;
    const int lane = t & 31;

    const float* vg = g_v + (size_t)bh * NPIX * DHEAD;

    if (t < 64) kds[t] = g_kdyn[b * NPIX + q0 + t];
    __syncthreads();

    for (int q = 0; q < 64; q++) {
        const uint32* row = (const uint32*)g_sim + ((size_t)bh * NPIX + q0 + q) * NPIX;
        const int base = t * 16;
        uint32 vals[16];
#pragma unroll
        for (int u = 0; u < 4; u++) {
            uint4 w = *(const uint4*)(row + base + u * 4);
            vals[u * 4 + 0] = w.x; vals[u * 4 + 1] = w.y;
            vals[u * 4 + 2] = w.z; vals[u * 4 + 3] = w.w;
        }
        // monotonic transform: unsigned ascending == float ascending
#pragma unroll
        for (int i = 0; i < 16; i++) {
            uint32 u = vals[i];
            vals[i] = (u & 0x80000000u) ? ~u : (u | 0x80000000u);
        }

        uint32 prefix = 0;
        int remaining = 32;     // rank we still need within the candidate set
#pragma unroll
        for (int lvl = 0; lvl < 4; lvl++) {
            const int sh = 24 - lvl * 8;
            const uint32 hiMask = (lvl == 0) ? 0u : (0xFFFFFFFFu << (32 - 8 * lvl));
            hist[t] = 0;
            __syncthreads();
#pragma unroll
            for (int i = 0; i < 16; i++) {
                uint32 v = vals[i];
                if ((v & hiMask) == prefix) atomicAdd(&hist[(v >> sh) & 0xFF], 1u);
            }
            __syncthreads();
            if (t < 32) {
                const int lo = 248 - t * 8;   // lane 0 owns top bins 248..255
                uint32 c[8]; uint32 csum = 0;
#pragma unroll
                for (int j = 0; j < 8; j++) { c[j] = hist[lo + j]; csum += c[j]; }
                uint32 inc = csum;
#pragma unroll
                for (int o = 1; o < 32; o <<= 1) {
                    uint32 x = __shfl_up_sync(0xffffffffu, inc, o);
                    if (t >= o) inc += x;
                }
                uint32 pre = inc - csum;      // count in strictly higher chunks
                if (pre < (uint32)remaining && inc >= (uint32)remaining) {
                    uint32 acc = pre; int sel = -1; uint32 before = 0;
#pragma unroll
                    for (int j = 7; j >= 0; j--) {
                        acc += c[j];
                        if (sel < 0 && acc >= (uint32)remaining) { sel = lo + j; before = acc - c[j]; }
                    }
                    bin_s = (uint32)sel; before_s = before;
                }
            }
            __syncthreads();
            prefix |= (bin_s << sh);
            remaining -= (int)before_s;
            __syncthreads();                  // protect bin_s/before_s for next level
        }
        const uint32 pivot = prefix;          // exact 32-bit key of the 32nd largest
        const int need = remaining;           // # pivot-equal entries to take (>=1)

        if (t == 0) cnt_s = 0;
        __syncthreads();
#pragma unroll
        for (int i = 0; i < 16; i++) {
            uint32 v = vals[i];
            if (v > pivot) { int p = atomicAdd(&cnt_s, 1); svals[p] = v; sidx[p] = base + i; }
        }
        __syncthreads();
        const int cg = cnt_s;                 // == 32 - need

        // pivot-equal entries: take the `need` smallest indices (lax.top_k tiebreak)
        int prevIdx = -1;
        for (int r = 0; r < need; r++) {
            if (t == 0) gmin_s = 0x7fffffff;
            __syncthreads();
            int best = 0x7fffffff;
#pragma unroll
            for (int i = 0; i < 16; i++) {
                if (vals[i] == pivot && (base + i) > prevIdx) { best = base + i; break; }
            }
            if (best != 0x7fffffff) atomicMin(&gmin_s, best);
            __syncthreads();
            int winner = gmin_s;
            if (t == 0) { svals[cg + r] = pivot; sidx[cg + r] = winner; }
            prevIdx = winner;
            __syncthreads();
        }

        // rank-sort the 32 selected (value desc, index asc) — exact permutation
        if (t < 32) {
            uint32 vi = svals[t]; int ii = sidx[t];
            int rank = 0;
#pragma unroll
            for (int j = 0; j < 32; j++) {
                uint32 vj = svals[j]; int ij = sidx[j];
                rank += (vj > vi) || (vj == vi && ij < ii);
            }
            uint32 fb = (vi & 0x80000000u) ? (vi ^ 0x80000000u) : ~vi;  // inverse transform
            sortv[rank] = __uint_as_float(fb);
            sorti[rank] = ii;
        }
        __syncthreads();

        // kd-mask softmax (warp 0)
        if (t < 32) {
            int kd = kds[q];
            float m = sortv[0];
            float e = (t < kd) ? expf(sortv[t] - m) : 0.f;
            float s = e;
#pragma unroll
            for (int o = 16; o; o >>= 1) s += __shfl_xor_sync(0xffffffffu, s, o);
            wsel[t] = e / s;
        }
        __syncthreads();

        // weighted v gather: 64 threads, one output dim each (coalesced v rows)
        if (t < 64) {
            float acc = 0.f;
#pragma unroll 4
            for (int s = 0; s < 32; s++)
                acc += wsel[s] * vg[(size_t)sorti[s] * DHEAD + t];
            outs[t * 65 + q] = acc;
        }
        __syncthreads();
    }

    // coalesced write: g_attn[b][h*64+d][q0+q]
    float* ab = g_attn + ((size_t)(b * CDIM + h * DHEAD)) * NPIX + q0;
    for (int e = t; e < 4096; e += 256) {
        int d = e >> 6, qq = e & 63;
        ab[(size_t)d * NPIX + qq] = outs[d * 65 + qq];
    }
}

// =====================================================================
// Kernel 4: proj conv + bias + residual. (unchanged from R7)
// =====================================================================
__global__ void __launch_bounds__(128) k_proj(const float* __restrict__ x,
                                              const float* __restrict__ w_proj,
                                              const float* __restrict__ b_proj,
                                              float* __restrict__ out)
{
    __shared__ __align__(16) float As[32 * 68];
    __shared__ __align__(16) float Bs[32 * 64];
    const int b  = blockIdx.z;
    const int o0 = blockIdx.y * 64;
    const int n0 = blockIdx.x * 64;
    const int t  = threadIdx.x;
    const int to = (t >> 3) * 4;
    const int tn = (t & 7) * 8;
    const float* ab = g_attn + (size_t)b * CDIM * NPIX;

    ull acc[4][4];
#pragma unroll
    for (int i = 0; i < 4; i++)
#pragma unroll
        for (int p = 0; p < 4; p++) acc[i][p] = 0ULL;

    for (int c0 = 0; c0 < CDIM; c0 += 32) {
#pragma unroll
        for (int r = 0; r < 4; r++) {
            int e = t + r * 128;
            int o_l = e >> 3;
            int c_l = (e & 7) * 4;
            float4 v4 = *(const float4*)(w_proj + (size_t)(o0 + o_l) * CDIM + c0 + c_l);
            As[(c_l + 0) * 68 + o_l] = v4.x;
            As[(c_l + 1) * 68 + o_l] = v4.y;
            As[(c_l + 2) * 68 + o_l] = v4.z;
            As[(c_l + 3) * 68 + o_l] = v4.w;
        }
#pragma unroll
        for (int r = 0; r < 4; r++) {
            int e = t + r * 128;
            int c_l = e >> 4;
            int n_l = (e & 15) * 4;
            *(float4*)(Bs + c_l * 64 + n_l) =
                *(const float4*)(ab + (size_t)(c0 + c_l) * NPIX + n0 + n_l);
        }
        __syncthreads();
#pragma unroll
        for (int cc = 0; cc < 32; cc++) {
            ull a[4], bb[4];
#pragma unroll
            for (int i = 0; i < 4; i++) a[i] = dup2(As[cc * 68 + to + i]);
            const ull* bp = (const ull*)(Bs + cc * 64 + tn);
#pragma unroll
            for (int p = 0; p < 4; p++) bb[p] = bp[p];
#pragma unroll
            for (int i = 0; i < 4; i++)
#pragma unroll
                for (int p = 0; p < 4; p++) acc[i][p] = fma2(a[i], bb[p], acc[i][p]);
        }
        __syncthreads();
    }

#pragma unroll
    for (int i = 0; i < 4; i++) {
        int o = o0 + to + i;
        float bp0 = b_proj[o];
#pragma unroll
        for (int p = 0; p < 4; p++) {
            int n = n0 + tn + 2 * p;
            size_t base = ((size_t)b * CDIM + o) * NPIX + n;
            out[base]     = lo2(acc[i][p]) + bp0 + x[base];
            out[base + 1] = hi2(acc[i][p]) + bp0 + x[base + 1];
        }
    }
}

// =====================================================================
extern "C" void kernel_launch(void* const* d_in, const int* in_sizes, int n_in,
                              void* d_out, int out_size)
{
    const float* x      = (const float*)d_in[0];
    const float* w_qkv  = (const float*)d_in[1];
    const float* w_proj = (const float*)d_in[2];
    const float* b_proj = (const float*)d_in[3];
    const float* w_g1   = (const float*)d_in[4];
    const float* b_g1   = (const float*)d_in[5];
    const float* w_g2   = (const float*)d_in[6];
    const float* b_g2   = (const float*)d_in[7];
    float* out = (float*)d_out;

    k_qkv<<<dim3(NPIX / 64, 26, BATCH), 128>>>(x, w_qkv, w_g1, b_g1);
    k_gate<<<(BATCH * NPIX) / 4, 128>>>(w_g2, b_g2);
    k_sim<<<dim3(NPIX / 64, BATCH * HEADS), 256>>>();
    k_select<<<dim3(NPIX / 64, BATCH * HEADS), 256>>>();
    k_proj<<<dim3(NPIX / 64, CDIM / 64, BATCH), 128>>>(x, w_proj, b_proj, out);
}

// round 12
// speedup vs baseline: 1.8380x; 1.2898x over previous
#include <cuda_runtime.h>
#include <math.h>

#define BATCH 2
#define CDIM  512
#define HEADS 8
#define DHEAD 64
#define NPIX  4096
#define KTOP  32
#define GDIM  128

typedef unsigned long long ull;
typedef unsigned int uint32;

#define NEG_INF (__int_as_float(0xff800000))

// ---------------- scratch (device globals; no allocation allowed) ----------------
__device__ float g_q[BATCH*HEADS*DHEAD*NPIX];   // [b][h][d][n]
__device__ float g_k[BATCH*HEADS*DHEAD*NPIX];   // [b][h][d][n]
__device__ float g_v[BATCH*HEADS*NPIX*DHEAD];   // [b][h][n][d]
__device__ float g_g1[BATCH*NPIX*GDIM];         // [b][n][o]  gate hidden (bias applied)
__device__ float g_attn[BATCH*CDIM*NPIX];       // [b][c][n]  attention output (pre-proj)
__device__ int   g_kdyn[BATCH*NPIX];
__device__ float g_sim[(size_t)BATCH*HEADS*NPIX*NPIX];  // [bh][q][j]  1.07 GB

// ---------------- f32x2 helpers (sm_103a packed fp32) ----------------
__device__ __forceinline__ ull fma2(ull a, ull b, ull c) {
    ull d;
    asm("fma.rn.f32x2 %0, %1, %2, %3;" : "=l"(d) : "l"(a), "l"(b), "l"(c));
    return d;
}
__device__ __forceinline__ ull dup2(float x) {
    ull r; unsigned u = __float_as_uint(x);
    asm("mov.b64 %0, {%1, %1};" : "=l"(r) : "r"(u));
    return r;
}
__device__ __forceinline__ float lo2(ull x) { return __uint_as_float((unsigned)x); }
__device__ __forceinline__ float hi2(ull x) { return __uint_as_float((unsigned)(x >> 32)); }

// =====================================================================
// Kernel 1: fused qkv conv (1536 rows) + gate conv1 (128 rows) GEMM.
// Bank-conflict-free b-loads: lane j-offset (t&7)*2, tile step 16.
// =====================================================================
__global__ void __launch_bounds__(128) k_qkv(const float* __restrict__ x,
                                             const float* __restrict__ w_qkv,
                                             const float* __restrict__ w_g1,
                                             const float* __restrict__ b_g1)
{
    __shared__ __align__(16) float As[32 * 68];
    __shared__ __align__(16) float Bs[32 * 64];
    const int b  = blockIdx.z;
    const int o0 = blockIdx.y * 64;
    const int n0 = blockIdx.x * 64;
    const int t  = threadIdx.x;
    const int to = (t >> 3) * 4;
    const int tn = (t & 7) * 2;          // interleaved: n = tn + p*16
    const float* xb = x + (size_t)b * CDIM * NPIX;

    ull acc[4][4];
#pragma unroll
    for (int i = 0; i < 4; i++)
#pragma unroll
        for (int p = 0; p < 4; p++) acc[i][p] = 0ULL;

    for (int c0 = 0; c0 < CDIM; c0 += 32) {
#pragma unroll
        for (int r = 0; r < 4; r++) {
            int e = t + r * 128;
            int o_l = e >> 3;
            int c_l = (e & 7) * 4;
            int o = o0 + o_l;
            const float* src = (o < 1536) ? (w_qkv + (size_t)o * CDIM + c0 + c_l)
                                          : (w_g1 + (size_t)(o - 1536) * CDIM + c0 + c_l);
            float4 v4 = *(const float4*)src;
            As[(c_l + 0) * 68 + o_l] = v4.x;
            As[(c_l + 1) * 68 + o_l] = v4.y;
            As[(c_l + 2) * 68 + o_l] = v4.z;
            As[(c_l + 3) * 68 + o_l] = v4.w;
        }
#pragma unroll
        for (int r = 0; r < 4; r++) {
            int e = t + r * 128;
            int c_l = e >> 4;
            int n_l = (e & 15) * 4;
            *(float4*)(Bs + c_l * 64 + n_l) =
                *(const float4*)(xb + (size_t)(c0 + c_l) * NPIX + n0 + n_l);
        }
        __syncthreads();
#pragma unroll
        for (int cc = 0; cc < 32; cc++) {
            ull a[4], bb[4];
#pragma unroll
            for (int i = 0; i < 4; i++) a[i] = dup2(As[cc * 68 + to + i]);
            const ull* bp = (const ull*)(Bs + cc * 64 + tn);
#pragma unroll
            for (int p = 0; p < 4; p++) bb[p] = bp[p * 8];   // +p*16 floats
#pragma unroll
            for (int i = 0; i < 4; i++)
#pragma unroll
                for (int p = 0; p < 4; p++) acc[i][p] = fma2(a[i], bb[p], acc[i][p]);
        }
        __syncthreads();
    }

#pragma unroll
    for (int i = 0; i < 4; i++) {
        int o = o0 + to + i;
#pragma unroll
        for (int p = 0; p < 4; p++) {
            int n = n0 + tn + p * 16;
            float v0 = lo2(acc[i][p]);
            float v1 = hi2(acc[i][p]);
            if (o < 512) {
                int h = o >> 6, d = o & 63;
                float* dst = g_q + (((size_t)(b * HEADS + h)) * DHEAD + d) * NPIX + n;
                dst[0] = v0; dst[1] = v1;
            } else if (o < 1024) {
                int oo = o - 512; int h = oo >> 6, d = oo & 63;
                float* dst = g_k + (((size_t)(b * HEADS + h)) * DHEAD + d) * NPIX + n;
                dst[0] = v0; dst[1] = v1;
            } else if (o < 1536) {
                int oo = o - 1024; int h = oo >> 6, d = oo & 63;
                float* dst = g_v + (((size_t)(b * HEADS + h)) * NPIX + n) * DHEAD + d;
                dst[0] = v0; dst[DHEAD] = v1;
            } else {
                int oo = o - 1536;
                float bg = b_g1[oo];
                float* dst = g_g1 + ((size_t)b * NPIX + n) * GDIM + oo;
                dst[0] = v0 + bg; dst[GDIM] = v1 + bg;
            }
        }
    }
}

// =====================================================================
// Kernel 2: gate second conv -> sigmoid -> dynamic k. (unchanged)
// =====================================================================
__global__ void __launch_bounds__(128) k_gate(const float* __restrict__ w_g2,
                                              const float* __restrict__ b_g2)
{
    int p = blockIdx.x * 4 + (threadIdx.x >> 5);
    int lane = threadIdx.x & 31;
    const float* g = g_g1 + (size_t)p * GDIM;
    float acc = 0.f;
#pragma unroll
    for (int r = 0; r < 4; r++) {
        int o = lane + r * 32;
        float gv = g[o];
        gv = gv > 0.f ? gv : 0.f;
        acc += gv * w_g2[o];
    }
#pragma unroll
    for (int s = 16; s; s >>= 1) acc += __shfl_xor_sync(0xffffffffu, acc, s);
    if (lane == 0) {
        float tau = 1.f / (1.f + expf(-(acc + b_g2[0])));
        int kd = (int)(tau * 32.f);
        kd = kd < 4 ? 4 : (kd > 32 ? 32 : kd);
        g_kdyn[p] = kd;
    }
}

// =====================================================================
// Kernel 3a: sim GEMM -> global. Conflict-free b-loads: lane j-offset
// (t&15)*2, tile step 32. Stores contiguous 128B per (i,p).
// grid (NPIX/64 qtiles, B*HEADS), 256 threads, 64x128 tiles.
// =====================================================================
__global__ void __launch_bounds__(256) k_sim()
{
    __shared__ __align__(16) float qs[4096];   // [64 d][64 q]
    __shared__ __align__(16) float ks[8192];   // [64 d][128 j]

    const int bh = blockIdx.y;
    const int q0 = blockIdx.x * 64;
    const int t  = threadIdx.x;

    const float* qg = g_q + (size_t)bh * DHEAD * NPIX;
    const float* kg = g_k + (size_t)bh * DHEAD * NPIX;

    for (int e = t; e < 1024; e += 256) {
        int d = e >> 4, i4 = (e & 15) * 4;
        *(float4*)(qs + d * 64 + i4) = *(const float4*)(qg + (size_t)d * NPIX + q0 + i4);
    }
    __syncthreads();

    const int tq  = (t >> 4) * 4;      // 4 query rows per thread
    const int tjl = (t & 15) * 2;      // interleaved: j = tjl + p*32

    for (int jt = 0; jt < 32; jt++) {
        for (int e = t; e < 2048; e += 256) {
            int d = e >> 5, j4 = (e & 31) * 4;
            *(float4*)(ks + d * 128 + j4) =
                *(const float4*)(kg + (size_t)d * NPIX + jt * 128 + j4);
        }
        __syncthreads();

        ull acc[4][4];
#pragma unroll
        for (int i = 0; i < 4; i++)
#pragma unroll
            for (int p = 0; p < 4; p++) acc[i][p] = 0ULL;
#pragma unroll 4
        for (int dd = 0; dd < 64; dd++) {
            ull a[4], bb[4];
#pragma unroll
            for (int i = 0; i < 4; i++) a[i] = dup2(qs[dd * 64 + tq + i]);
            const ull* bp = (const ull*)(ks + dd * 128 + tjl);
#pragma unroll
            for (int p = 0; p < 4; p++) bb[p] = bp[p * 16];   // +p*32 floats
#pragma unroll
            for (int i = 0; i < 4; i++)
#pragma unroll
                for (int p = 0; p < 4; p++) acc[i][p] = fma2(a[i], bb[p], acc[i][p]);
        }

#pragma unroll
        for (int i = 0; i < 4; i++) {
            float* srow = g_sim + ((size_t)bh * NPIX + q0 + tq + i) * NPIX + jt * 128 + tjl;
#pragma unroll
            for (int p = 0; p < 4; p++) {
                float2 st = make_float2(lo2(acc[i][p]) * 0.125f, hi2(acc[i][p]) * 0.125f);
                *(float2*)(srow + p * 32) = st;
            }
        }
        __syncthreads();
    }
}

// =====================================================================
// Kernel 3b: exact per-query top-32 (radix select on monotonic uint) +
//            kd-mask softmax + weighted v gather + coalesced output.
// (unchanged from passing R11 kernel)
// =====================================================================
__global__ void __launch_bounds__(256) k_select()
{
    __shared__ uint32 hist[256];
    __shared__ uint32 svals[32];
    __shared__ int    sidx[32];
    __shared__ float  sortv[32];
    __shared__ int    sorti[32];
    __shared__ float  wsel[32];
    __shared__ int    kds[64];
    __shared__ float  outs[64 * 65];
    __shared__ uint32 bin_s, before_s;
    __shared__ int    cnt_s, gmin_s;

    const int bh = blockIdx.y;
    const int b  = bh >> 3;
    const int h  = bh & 7;
    const int q0 = blockIdx.x * 64;
    const int t  = threadIdx.x;

    const float* vg = g_v + (size_t)bh * NPIX * DHEAD;

    if (t < 64) kds[t] = g_kdyn[b * NPIX + q0 + t];
    __syncthreads();

    for (int q = 0; q < 64; q++) {
        const uint32* row = (const uint32*)g_sim + ((size_t)bh * NPIX + q0 + q) * NPIX;
        const int base = t * 16;
        uint32 vals[16];
#pragma unroll
        for (int u = 0; u < 4; u++) {
            uint4 w = *(const uint4*)(row + base + u * 4);
            vals[u * 4 + 0] = w.x; vals[u * 4 + 1] = w.y;
            vals[u * 4 + 2] = w.z; vals[u * 4 + 3] = w.w;
        }
#pragma unroll
        for (int i = 0; i < 16; i++) {
            uint32 u = vals[i];
            vals[i] = (u & 0x80000000u) ? ~u : (u | 0x80000000u);
        }

        uint32 prefix = 0;
        int remaining = 32;
#pragma unroll
        for (int lvl = 0; lvl < 4; lvl++) {
            const int sh = 24 - lvl * 8;
            const uint32 hiMask = (lvl == 0) ? 0u : (0xFFFFFFFFu << (32 - 8 * lvl));
            hist[t] = 0;
            __syncthreads();
#pragma unroll
            for (int i = 0; i < 16; i++) {
                uint32 v = vals[i];
                if ((v & hiMask) == prefix) atomicAdd(&hist[(v >> sh) & 0xFF], 1u);
            }
            __syncthreads();
            if (t < 32) {
                const int lo = 248 - t * 8;
                uint32 c[8]; uint32 csum = 0;
#pragma unroll
                for (int j = 0; j < 8; j++) { c[j] = hist[lo + j]; csum += c[j]; }
                uint32 inc = csum;
#pragma unroll
                for (int o = 1; o < 32; o <<= 1) {
                    uint32 x = __shfl_up_sync(0xffffffffu, inc, o);
                    if (t >= o) inc += x;
                }
                uint32 pre = inc - csum;
                if (pre < (uint32)remaining && inc >= (uint32)remaining) {
                    uint32 acc = pre; int sel = -1; uint32 before = 0;
#pragma unroll
                    for (int j = 7; j >= 0; j--) {
                        acc += c[j];
                        if (sel < 0 && acc >= (uint32)remaining) { sel = lo + j; before = acc - c[j]; }
                    }
                    bin_s = (uint32)sel; before_s = before;
                }
            }
            __syncthreads();
            prefix |= (bin_s << sh);
            remaining -= (int)before_s;
            __syncthreads();
        }
        const uint32 pivot = prefix;
        const int need = remaining;

        if (t == 0) cnt_s = 0;
        __syncthreads();
#pragma unroll
        for (int i = 0; i < 16; i++) {
            uint32 v = vals[i];
            if (v > pivot) { int p = atomicAdd(&cnt_s, 1); svals[p] = v; sidx[p] = base + i; }
        }
        __syncthreads();
        const int cg = cnt_s;

        int prevIdx = -1;
        for (int r = 0; r < need; r++) {
            if (t == 0) gmin_s = 0x7fffffff;
            __syncthreads();
            int best = 0x7fffffff;
#pragma unroll
            for (int i = 0; i < 16; i++) {
                if (vals[i] == pivot && (base + i) > prevIdx) { best = base + i; break; }
            }
            if (best != 0x7fffffff) atomicMin(&gmin_s, best);
            __syncthreads();
            int winner = gmin_s;
            if (t == 0) { svals[cg + r] = pivot; sidx[cg + r] = winner; }
            prevIdx = winner;
            __syncthreads();
        }

        if (t < 32) {
            uint32 vi = svals[t]; int ii = sidx[t];
            int rank = 0;
#pragma unroll
            for (int j = 0; j < 32; j++) {
                uint32 vj = svals[j]; int ij = sidx[j];
                rank += (vj > vi) || (vj == vi && ij < ii);
            }
            uint32 fb = (vi & 0x80000000u) ? (vi ^ 0x80000000u) : ~vi;
            sortv[rank] = __uint_as_float(fb);
            sorti[rank] = ii;
        }
        __syncthreads();

        if (t < 32) {
            int kd = kds[q];
            float m = sortv[0];
            float e = (t < kd) ? expf(sortv[t] - m) : 0.f;
            float s = e;
#pragma unroll
            for (int o = 16; o; o >>= 1) s += __shfl_xor_sync(0xffffffffu, s, o);
            wsel[t] = e / s;
        }
        __syncthreads();

        if (t < 64) {
            float acc = 0.f;
#pragma unroll 4
            for (int s = 0; s < 32; s++)
                acc += wsel[s] * vg[(size_t)sorti[s] * DHEAD + t];
            outs[t * 65 + q] = acc;
        }
        __syncthreads();
    }

    float* ab = g_attn + ((size_t)(b * CDIM + h * DHEAD)) * NPIX + q0;
    for (int e = t; e < 4096; e += 256) {
        int d = e >> 6, qq = e & 63;
        ab[(size_t)d * NPIX + qq] = outs[d * 65 + qq];
    }
}

// =====================================================================
// Kernel 4: proj conv + bias + residual. Conflict-free b-loads.
// =====================================================================
__global__ void __launch_bounds__(128) k_proj(const float* __restrict__ x,
                                              const float* __restrict__ w_proj,
                                              const float* __restrict__ b_proj,
                                              float* __restrict__ out)
{
    __shared__ __align__(16) float As[32 * 68];
    __shared__ __align__(16) float Bs[32 * 64];
    const int b  = blockIdx.z;
    const int o0 = blockIdx.y * 64;
    const int n0 = blockIdx.x * 64;
    const int t  = threadIdx.x;
    const int to = (t >> 3) * 4;
    const int tn = (t & 7) * 2;          // interleaved: n = tn + p*16
    const float* ab = g_attn + (size_t)b * CDIM * NPIX;

    ull acc[4][4];
#pragma unroll
    for (int i = 0; i < 4; i++)
#pragma unroll
        for (int p = 0; p < 4; p++) acc[i][p] = 0ULL;

    for (int c0 = 0; c0 < CDIM; c0 += 32) {
#pragma unroll
        for (int r = 0; r < 4; r++) {
            int e = t + r * 128;
            int o_l = e >> 3;
            int c_l = (e & 7) * 4;
            float4 v4 = *(const float4*)(w_proj + (size_t)(o0 + o_l) * CDIM + c0 + c_l);
            As[(c_l + 0) * 68 + o_l] = v4.x;
            As[(c_l + 1) * 68 + o_l] = v4.y;
            As[(c_l + 2) * 68 + o_l] = v4.z;
            As[(c_l + 3) * 68 + o_l] = v4.w;
        }
#pragma unroll
        for (int r = 0; r < 4; r++) {
            int e = t + r * 128;
            int c_l = e >> 4;
            int n_l = (e & 15) * 4;
            *(float4*)(Bs + c_l * 64 + n_l) =
                *(const float4*)(ab + (size_t)(c0 + c_l) * NPIX + n0 + n_l);
        }
        __syncthreads();
#pragma unroll
        for (int cc = 0; cc < 32; cc++) {
            ull a[4], bb[4];
#pragma unroll
            for (int i = 0; i < 4; i++) a[i] = dup2(As[cc * 68 + to + i]);
            const ull* bp = (const ull*)(Bs + cc * 64 + tn);
#pragma unroll
            for (int p = 0; p < 4; p++) bb[p] = bp[p * 8];   // +p*16 floats
#pragma unroll
            for (int i = 0; i < 4; i++)
#pragma unroll
                for (int p = 0; p < 4; p++) acc[i][p] = fma2(a[i], bb[p], acc[i][p]);
        }
        __syncthreads();
    }

#pragma unroll
    for (int i = 0; i < 4; i++) {
        int o = o0 + to + i;
        float bp0 = b_proj[o];
#pragma unroll
        for (int p = 0; p < 4; p++) {
            int n = n0 + tn + p * 16;
            size_t base = ((size_t)b * CDIM + o) * NPIX + n;
            out[base]     = lo2(acc[i][p]) + bp0 + x[base];
            out[base + 1] = hi2(acc[i][p]) + bp0 + x[base + 1];
        }
    }
}

// =====================================================================
extern "C" void kernel_launch(void* const* d_in, const int* in_sizes, int n_in,
                              void* d_out, int out_size)
{
    const float* x      = (const float*)d_in[0];
    const float* w_qkv  = (const float*)d_in[1];
    const float* w_proj = (const float*)d_in[2];
    const float* b_proj = (const float*)d_in[3];
    const float* w_g1   = (const float*)d_in[4];
    const float* b_g1   = (const float*)d_in[5];
    const float* w_g2   = (const float*)d_in[6];
    const float* b_g2   = (const float*)d_in[7];
    float* out = (float*)d_out;

    k_qkv<<<dim3(NPIX / 64, 26, BATCH), 128>>>(x, w_qkv, w_g1, b_g1);
    k_gate<<<(BATCH * NPIX) / 4, 128>>>(w_g2, b_g2);
    k_sim<<<dim3(NPIX / 64, BATCH * HEADS), 256>>>();
    k_select<<<dim3(NPIX / 64, BATCH * HEADS), 256>>>();
    k_proj<<<dim3(NPIX / 64, CDIM / 64, BATCH), 128>>>(x, w_proj, b_proj, out);
}